// round 11
// baseline (speedup 1.0000x reference)
#include <cuda_runtime.h>
#include <cuda_bf16.h>
#include <math.h>
#include <cstdint>

// Problem constants: B=2, N=8192, DIM=512, H=8, A=256, D=64
__device__ float g_qkv[16384 * 1536];        // qkv scratch (fp32)
__device__ float g_kv [16 * 256 * 64];       // fused num -> normalized kv
__device__ float g_ksum[16 * 256];           // softmax denominators
__device__ float g_tsum;
// bf16 hi/lo split buffers
__device__ __align__(16) __nv_bfloat16 g_xh[16384 * 512];
__device__ __align__(16) __nv_bfloat16 g_xl[16384 * 512];
__device__ __align__(16) __nv_bfloat16 g_wh[1536 * 512];
__device__ __align__(16) __nv_bfloat16 g_wl[1536 * 512];
__device__ __align__(16) __nv_bfloat16 g_agh[8 * 256 * 64];
__device__ __align__(16) __nv_bfloat16 g_agl[8 * 256 * 64];
// kv2 transposed [bh][d][a], bf16 hi/lo
__device__ __align__(16) __nv_bfloat16 g_kt_h[16 * 64 * 256];
__device__ __align__(16) __nv_bfloat16 g_kt_l[16 * 64 * 256];

// ===========================================================================
// PTX helpers
// ===========================================================================
__device__ __forceinline__ uint32_t smem_to_u32(const void* p) {
    uint32_t a;
    asm("{ .reg .u64 t; cvta.to.shared.u64 t, %1; cvt.u32.u64 %0, t; }" : "=r"(a) : "l"(p));
    return a;
}
#define LDMATRIX_X4(r0, r1, r2, r3, addr) \
    asm volatile("ldmatrix.sync.aligned.m8n8.x4.shared.b16 {%0,%1,%2,%3}, [%4];" \
                 : "=r"(r0), "=r"(r1), "=r"(r2), "=r"(r3) : "r"(addr))
#define LDMATRIX_X4_T(r0, r1, r2, r3, addr) \
    asm volatile("ldmatrix.sync.aligned.m8n8.x4.trans.shared.b16 {%0,%1,%2,%3}, [%4];" \
                 : "=r"(r0), "=r"(r1), "=r"(r2), "=r"(r3) : "r"(addr))
#define MMA_BF16(c, a, b) \
    asm volatile("mma.sync.aligned.m16n8k16.row.col.f32.bf16.bf16.f32 " \
                 "{%0,%1,%2,%3}, {%4,%5,%6,%7}, {%8,%9}, {%0,%1,%2,%3};" \
                 : "+f"((c)[0]), "+f"((c)[1]), "+f"((c)[2]), "+f"((c)[3]) \
                 : "r"((a)[0]), "r"((a)[1]), "r"((a)[2]), "r"((a)[3]), \
                   "r"((b)[0]), "r"((b)[1]))
#define CP_ASYNC16(dst, src) \
    asm volatile("cp.async.cg.shared.global [%0], [%1], 16;" :: "r"(dst), "l"(src))
#define CP_COMMIT() asm volatile("cp.async.commit_group;" ::: "memory")
#define CP_WAIT0()  asm volatile("cp.async.wait_group 0;" ::: "memory")

// pack two floats -> bf16x2 hi word and residual lo word
__device__ __forceinline__ void split2(float a, float b, uint32_t& h, uint32_t& l) {
    __nv_bfloat16 ha = __float2bfloat16_rn(a), hb = __float2bfloat16_rn(b);
    __nv_bfloat162 hp; hp.x = ha; hp.y = hb;
    __nv_bfloat162 lp;
    lp.x = __float2bfloat16_rn(a - __bfloat162float(ha));
    lp.y = __float2bfloat16_rn(b - __bfloat162float(hb));
    h = *(uint32_t*)&hp; l = *(uint32_t*)&lp;
}

// ===========================================================================
// bf16 split kernel
// ===========================================================================
__global__ __launch_bounds__(256)
void split_bf16(const float* __restrict__ in, __nv_bfloat16* __restrict__ hi,
                __nv_bfloat16* __restrict__ lo, long n) {
    for (long i = ((long)blockIdx.x * blockDim.x + threadIdx.x) * 4; i < n;
         i += (long)gridDim.x * blockDim.x * 4) {
        float4 v = *(const float4*)(in + i);
        uint32_t h01, h23, l01, l23;
        split2(v.x, v.y, h01, l01);
        split2(v.z, v.w, h23, l23);
        *(uint2*)(hi + i) = make_uint2(h01, h23);
        *(uint2*)(lo + i) = make_uint2(l01, l23);
    }
}

// ===========================================================================
// K1: C[16384,1536] = X[16384,512] @ W[1536,512]^T via bf16x3 mma.sync.
// Retiled: CTA 128x128, 4 warps (2m x 2n), warp tile 64x64, BK=32.
// Halves LDSM redundancy vs the 8-warp 64x32 version (smem-port bound fix).
// ===========================================================================
static constexpr int K1_ROWB = 80;
static constexpr int K1_BUF  = 128 * K1_ROWB;
static constexpr int K1_STAGE = 4 * K1_BUF;
static constexpr int K1_SMEM  = 2 * K1_STAGE;

__global__ __launch_bounds__(128)
void k1_mma_kernel(const __nv_bfloat16* __restrict__ xh,
                   const __nv_bfloat16* __restrict__ xl,
                   const __nv_bfloat16* __restrict__ wh,
                   const __nv_bfloat16* __restrict__ wl,
                   float* __restrict__ C)
{
    extern __shared__ char smem[];
    uint32_t sb = smem_to_u32(smem);
    int tid = threadIdx.x;
    int lane = tid & 31, wid = tid >> 5;
    int mw = wid & 1, nw = wid >> 1;           // 2m x 2n warps
    int nt = blockIdx.x, mt = blockIdx.y;

    const __nv_bfloat16* srcA_h = xh + (long)(mt * 128) * 512;
    const __nv_bfloat16* srcA_l = xl + (long)(mt * 128) * 512;
    const __nv_bfloat16* srcB_h = wh + (long)(nt * 128) * 512;
    const __nv_bfloat16* srcB_l = wl + (long)(nt * 128) * 512;

    float acc[4][8][4];
#pragma unroll
    for (int i = 0; i < 4; i++)
#pragma unroll
        for (int j = 0; j < 8; j++)
#pragma unroll
            for (int q = 0; q < 4; q++) acc[i][j][q] = 0.f;

    int a_tile = lane >> 3, a_rin = lane & 7;
    int a_row = a_rin + (a_tile & 1) * 8;
    int a_kb  = (a_tile >> 1) * 16;
    int b_row = (a_tile >> 1) * 8 + a_rin;
    int b_kb  = (a_tile & 1) * 16;

    auto issue_loads = [&](int stage, int k0) {
        uint32_t base = sb + stage * K1_STAGE;
#pragma unroll
        for (int j = 0; j < 16; j++) {
            int idx = tid + j * 128;
            int buf = idx >> 9;
            int r   = (idx >> 2) & 127;
            int g   = idx & 3;
            const __nv_bfloat16* src =
                (buf == 0 ? srcA_h : buf == 1 ? srcA_l : buf == 2 ? srcB_h : srcB_l)
                + (long)r * 512 + k0 + g * 8;
            uint32_t dst = base + buf * K1_BUF + r * K1_ROWB + g * 16;
            CP_ASYNC16(dst, src);
        }
    };

    issue_loads(0, 0);
    CP_COMMIT(); CP_WAIT0();
    __syncthreads();

    for (int kc = 0; kc < 16; ++kc) {
        int cur = kc & 1;
        if (kc < 15) { issue_loads(cur ^ 1, (kc + 1) * 32); CP_COMMIT(); }

        uint32_t st = sb + cur * K1_STAGE;
        uint32_t Ah = st,              Al = st + K1_BUF;
        uint32_t Bh = st + 2 * K1_BUF, Bl = st + 3 * K1_BUF;

#pragma unroll
        for (int s = 0; s < 2; ++s) {
            int skb = s * 32;
            uint32_t ah[4][4], al[4][4];
#pragma unroll
            for (int mf = 0; mf < 4; mf++) {
                uint32_t addr = Ah + (mw * 64 + mf * 16 + a_row) * K1_ROWB + skb + a_kb;
                LDMATRIX_X4(ah[mf][0], ah[mf][1], ah[mf][2], ah[mf][3], addr);
                uint32_t addr2 = Al + (mw * 64 + mf * 16 + a_row) * K1_ROWB + skb + a_kb;
                LDMATRIX_X4(al[mf][0], al[mf][1], al[mf][2], al[mf][3], addr2);
            }
#pragma unroll
            for (int p = 0; p < 4; p++) {
                uint32_t b_h[2][2], b_l[2][2];
                uint32_t ad = Bh + (nw * 64 + p * 16 + b_row) * K1_ROWB + skb + b_kb;
                LDMATRIX_X4(b_h[0][0], b_h[0][1], b_h[1][0], b_h[1][1], ad);
                uint32_t ad2 = Bl + (nw * 64 + p * 16 + b_row) * K1_ROWB + skb + b_kb;
                LDMATRIX_X4(b_l[0][0], b_l[0][1], b_l[1][0], b_l[1][1], ad2);
                // term ordering: hh all, hl all, lh all (dep distance 8)
#pragma unroll
                for (int mf = 0; mf < 4; mf++)
#pragma unroll
                    for (int j = 0; j < 2; j++) MMA_BF16(acc[mf][p * 2 + j], ah[mf], b_h[j]);
#pragma unroll
                for (int mf = 0; mf < 4; mf++)
#pragma unroll
                    for (int j = 0; j < 2; j++) MMA_BF16(acc[mf][p * 2 + j], ah[mf], b_l[j]);
#pragma unroll
                for (int mf = 0; mf < 4; mf++)
#pragma unroll
                    for (int j = 0; j < 2; j++) MMA_BF16(acc[mf][p * 2 + j], al[mf], b_h[j]);
            }
        }

        if (kc < 15) CP_WAIT0();
        __syncthreads();
    }

    int rbase = mt * 128 + mw * 64 + (lane >> 2);
    int cbase = nt * 128 + nw * 64 + (lane & 3) * 2;
#pragma unroll
    for (int mf = 0; mf < 4; mf++)
#pragma unroll
        for (int nf = 0; nf < 8; nf++) {
            long r0 = rbase + mf * 16;
            long cc = cbase + nf * 8;
            *(float2*)(C + r0 * 1536 + cc)       = make_float2(acc[mf][nf][0], acc[mf][nf][1]);
            *(float2*)(C + (r0 + 8) * 1536 + cc) = make_float2(acc[mf][nf][2], acc[mf][nf][3]);
        }
}

// ===========================================================================
// init: zero atomic accumulators
// ===========================================================================
__global__ void init_kernel() {
    int i = blockIdx.x * blockDim.x + threadIdx.x;
    if (i == 0) g_tsum = 0.f;
    if (i < 16 * 256) g_ksum[i] = 0.f;
    for (; i < 16 * 256 * 64; i += gridDim.x * blockDim.x) g_kv[i] = 0.f;
}

// ===========================================================================
// Fused stage A: kv-partials (S = agent@K^T, P=exp, num+=P@V, den+=rowsum)
// grid (8, 16), 256 threads.
// ===========================================================================
static constexpr int A_STR   = 144;
static constexpr int A_AGL   = 36864;
static constexpr int A_KH    = 73728;
static constexpr int A_KL    = A_KH + 4608;
static constexpr int A_VH    = A_KH + 9216;
static constexpr int A_VL    = A_KH + 13824;
static constexpr int A_SMEM  = 92160;

__global__ __launch_bounds__(256)
void attn_kv_kernel(const float* __restrict__ qkv,
                    const __nv_bfloat16* __restrict__ agh,
                    const __nv_bfloat16* __restrict__ agl,
                    float* __restrict__ kv, float* __restrict__ ksum)
{
    extern __shared__ char smem[];
    char* sc = smem;
    uint32_t sb = smem_to_u32(smem);
    int tid = threadIdx.x, lane = tid & 31, wid = tid >> 5;
    int split = blockIdx.x, bh = blockIdx.y;
    int b = bh >> 3, h = bh & 7;
    int t8 = lane >> 3, rin = lane & 7;
    int a_row = rin + (t8 & 1) * 8, a_kb = (t8 >> 1) * 16;
    int b_row = (t8 >> 1) * 8 + rin, b_kb = (t8 & 1) * 16;
    int v_row = (t8 & 1) * 8 + rin, v_cb = (t8 >> 1) * 16;

    // ---- agent hi/lo via cp.async (presplit)
    {
        const __nv_bfloat16* ah_p = agh + h * 16384;
        const __nv_bfloat16* al_p = agl + h * 16384;
        for (int i = tid; i < 2048; i += 256) {
            int r = i >> 3, c = i & 7;
            CP_ASYNC16(sb + r * A_STR + c * 16,         ah_p + r * 64 + c * 8);
            CP_ASYNC16(sb + A_AGL + r * A_STR + c * 16, al_p + r * 64 + c * 8);
        }
        CP_COMMIT();
    }

    float kvacc[2][8][4];
#pragma unroll
    for (int i = 0; i < 2; i++)
#pragma unroll
        for (int j = 0; j < 8; j++)
#pragma unroll
            for (int q = 0; q < 4; q++) kvacc[i][j][q] = 0.f;
    float rs[2][2] = {{0.f, 0.f}, {0.f, 0.f}};

    const float* kbase = qkv + 512 + h * 64 + (long)(b * 8192 + split * 1024) * 1536;
    int lr = tid >> 3, lc = tid & 7;

    float4 pk0, pk1, pv0, pv1;
    {
        const float* kr = kbase + (long)lr * 1536 + lc * 8;
        pk0 = *(const float4*)kr;         pk1 = *(const float4*)(kr + 4);
        pv0 = *(const float4*)(kr + 512); pv1 = *(const float4*)(kr + 516);
    }
    CP_WAIT0();
    __syncthreads();

    for (int t = 0; t < 32; ++t) {
        {
            uint32_t x0, x1, x2, x3, y0, y1, y2, y3;
            split2(pk0.x, pk0.y, x0, y0); split2(pk0.z, pk0.w, x1, y1);
            split2(pk1.x, pk1.y, x2, y2); split2(pk1.z, pk1.w, x3, y3);
            *(uint4*)(sc + A_KH + lr * A_STR + lc * 16) = make_uint4(x0, x1, x2, x3);
            *(uint4*)(sc + A_KL + lr * A_STR + lc * 16) = make_uint4(y0, y1, y2, y3);
            split2(pv0.x, pv0.y, x0, y0); split2(pv0.z, pv0.w, x1, y1);
            split2(pv1.x, pv1.y, x2, y2); split2(pv1.z, pv1.w, x3, y3);
            *(uint4*)(sc + A_VH + lr * A_STR + lc * 16) = make_uint4(x0, x1, x2, x3);
            *(uint4*)(sc + A_VL + lr * A_STR + lc * 16) = make_uint4(y0, y1, y2, y3);
        }
        __syncthreads();
        if (t < 31) {
            const float* kr = kbase + (long)((t + 1) * 32 + lr) * 1536 + lc * 8;
            pk0 = *(const float4*)kr;         pk1 = *(const float4*)(kr + 4);
            pv0 = *(const float4*)(kr + 512); pv1 = *(const float4*)(kr + 516);
        }

        float s[2][4][4];
#pragma unroll
        for (int i = 0; i < 2; i++)
#pragma unroll
            for (int j = 0; j < 4; j++)
#pragma unroll
                for (int q = 0; q < 4; q++) s[i][j][q] = 0.f;

#pragma unroll
        for (int kf = 0; kf < 4; ++kf) {
            uint32_t ah[2][4], al[2][4];
#pragma unroll
            for (int mf = 0; mf < 2; ++mf) {
                uint32_t ad = sb + (wid * 32 + mf * 16 + a_row) * A_STR + kf * 32 + a_kb;
                LDMATRIX_X4(ah[mf][0], ah[mf][1], ah[mf][2], ah[mf][3], ad);
                LDMATRIX_X4(al[mf][0], al[mf][1], al[mf][2], al[mf][3], ad + A_AGL);
            }
            uint32_t kbh[4][2], kbl[4][2];
#pragma unroll
            for (int p = 0; p < 2; ++p) {
                uint32_t ad = sb + A_KH + (p * 16 + b_row) * A_STR + kf * 32 + b_kb;
                LDMATRIX_X4(kbh[p * 2][0], kbh[p * 2][1], kbh[p * 2 + 1][0], kbh[p * 2 + 1][1], ad);
                LDMATRIX_X4(kbl[p * 2][0], kbl[p * 2][1], kbl[p * 2 + 1][0], kbl[p * 2 + 1][1], ad + 4608);
            }
#pragma unroll
            for (int mf = 0; mf < 2; ++mf)
#pragma unroll
                for (int nf = 0; nf < 4; ++nf) {
                    MMA_BF16(s[mf][nf], ah[mf], kbh[nf]);
                    MMA_BF16(s[mf][nf], ah[mf], kbl[nf]);
                    MMA_BF16(s[mf][nf], al[mf], kbh[nf]);
                }
        }

        uint32_t ph[2][2][4], pl[2][2][4];
#pragma unroll
        for (int mf = 0; mf < 2; ++mf) {
#pragma unroll
            for (int nf = 0; nf < 4; ++nf) {
                s[mf][nf][0] = __expf(s[mf][nf][0]);
                s[mf][nf][1] = __expf(s[mf][nf][1]);
                s[mf][nf][2] = __expf(s[mf][nf][2]);
                s[mf][nf][3] = __expf(s[mf][nf][3]);
                rs[mf][0] += s[mf][nf][0] + s[mf][nf][1];
                rs[mf][1] += s[mf][nf][2] + s[mf][nf][3];
            }
#pragma unroll
            for (int kt = 0; kt < 2; ++kt) {
                split2(s[mf][2 * kt][0],     s[mf][2 * kt][1],     ph[mf][kt][0], pl[mf][kt][0]);
                split2(s[mf][2 * kt][2],     s[mf][2 * kt][3],     ph[mf][kt][1], pl[mf][kt][1]);
                split2(s[mf][2 * kt + 1][0], s[mf][2 * kt + 1][1], ph[mf][kt][2], pl[mf][kt][2]);
                split2(s[mf][2 * kt + 1][2], s[mf][2 * kt + 1][3], ph[mf][kt][3], pl[mf][kt][3]);
            }
        }

#pragma unroll
        for (int kt = 0; kt < 2; ++kt) {
#pragma unroll
            for (int p = 0; p < 4; ++p) {
                uint32_t bvh[2][2], bvl[2][2];
                uint32_t ad = sb + A_VH + (kt * 16 + v_row) * A_STR + p * 32 + v_cb;
                LDMATRIX_X4_T(bvh[0][0], bvh[0][1], bvh[1][0], bvh[1][1], ad);
                LDMATRIX_X4_T(bvl[0][0], bvl[0][1], bvl[1][0], bvl[1][1], ad + 4608);
#pragma unroll
                for (int mf = 0; mf < 2; ++mf)
#pragma unroll
                    for (int j = 0; j < 2; ++j) {
                        int nf = p * 2 + j;
                        MMA_BF16(kvacc[mf][nf], ph[mf][kt], bvh[j]);
                        MMA_BF16(kvacc[mf][nf], ph[mf][kt], bvl[j]);
                        MMA_BF16(kvacc[mf][nf], pl[mf][kt], bvh[j]);
                    }
            }
        }
        __syncthreads();
    }

#pragma unroll
    for (int mf = 0; mf < 2; ++mf)
#pragma unroll
        for (int j = 0; j < 2; ++j) {
            float r = rs[mf][j];
            r += __shfl_xor_sync(0xffffffffu, r, 1);
            r += __shfl_xor_sync(0xffffffffu, r, 2);
            if ((lane & 3) == 0)
                atomicAdd(&ksum[bh * 256 + wid * 32 + mf * 16 + j * 8 + (lane >> 2)], r);
        }
    float* kvb = kv + bh * 16384;
#pragma unroll
    for (int mf = 0; mf < 2; ++mf)
#pragma unroll
        for (int nf = 0; nf < 8; ++nf) {
            int r0 = wid * 32 + mf * 16 + (lane >> 2);
            int c  = nf * 8 + (lane & 3) * 2;
            atomicAdd(&kvb[r0 * 64 + c],           kvacc[mf][nf][0]);
            atomicAdd(&kvb[r0 * 64 + c + 1],       kvacc[mf][nf][1]);
            atomicAdd(&kvb[(r0 + 8) * 64 + c],     kvacc[mf][nf][2]);
            atomicAdd(&kvb[(r0 + 8) * 64 + c + 1], kvacc[mf][nf][3]);
        }
}

// kv /= ksum
__global__ __launch_bounds__(256)
void kv_div_kernel(float* __restrict__ kv, const float* __restrict__ ksum) {
    int i = blockIdx.x * 256 + threadIdx.x;
    kv[i] = kv[i] / ksum[i >> 6];
}

// thresh: tsum = sum_i kv_flat[i] * w_thresh[i % 512]
__global__ __launch_bounds__(256)
void thresh_kernel(const float* __restrict__ kv, const float* __restrict__ wth)
{
    __shared__ float red[256];
    float s = 0.f;
    for (long i = blockIdx.x * 256 + threadIdx.x; i < 16L * 256 * 64;
         i += (long)gridDim.x * 256) {
        s += kv[i] * wth[i & 511];
    }
    red[threadIdx.x] = s; __syncthreads();
    for (int st = 128; st > 0; st >>= 1) {
        if (threadIdx.x < st) red[threadIdx.x] += red[threadIdx.x + st];
        __syncthreads();
    }
    if (threadIdx.x == 0) atomicAdd(&g_tsum, red[0]);
}

__device__ __forceinline__ float sigmoidf_(float x) { return 1.f / (1.f + expf(-x)); }

// ===========================================================================
// kv2 = softmax_d(kv*mask + denoise); write TRANSPOSED bf16 hi/lo [bh][d][a]
// ===========================================================================
__global__ __launch_bounds__(64)
void kv2_kernel(const float* __restrict__ kv,
                __nv_bfloat16* __restrict__ kth, __nv_bfloat16* __restrict__ ktl,
                const float* __restrict__ wn, const float* __restrict__ bn,
                const float* __restrict__ wm, const float* __restrict__ bm,
                const float* __restrict__ bth)
{
    long r = blockIdx.x;
    int bh = (int)(r >> 8), a = (int)(r & 255);
    int d = threadIdx.x;
    __shared__ float kr[64];
    __shared__ float tmp[64];

    kr[d] = kv[r * 64 + d];
    __syncthreads();

    float thresh = sigmoidf_(g_tsum * (1.f / 512.f) + bth[0]);

    float sn = bn[d], sm = bm[d];
#pragma unroll 8
    for (int e = 0; e < 64; e++) {
        float ke = kr[e];
        sn += ke * wn[d * 64 + e];
        sm += ke * wm[d * 64 + e];
    }
    float denoise = sigmoidf_(sn);
    float mval    = sigmoidf_(sm);
    float mbin    = (mval > thresh) ? 1.f : 0.f;
    float val     = kr[d] * mbin + denoise;

    tmp[d] = val; __syncthreads();
    float mx = -3.4e38f;
    for (int e = 0; e < 64; e++) mx = fmaxf(mx, tmp[e]);
    __syncthreads();
    float ev = expf(val - mx);
    tmp[d] = ev; __syncthreads();
    float sum = 0.f;
    for (int e = 0; e < 64; e++) sum += tmp[e];
    float v = ev / sum;
    __nv_bfloat16 hh = __float2bfloat16_rn(v);
    kth[bh * 16384 + d * 256 + a] = hh;
    ktl[bh * 16384 + d * 256 + a] = __float2bfloat16_rn(v - __bfloat162float(hh));
}

// ===========================================================================
// Fused stage B: L=(q/8)@agent^T, P=exp(L), O=P@kv2^T, out=O/rowsum
// grid (128, 16), 256 threads.
// ===========================================================================
static constexpr int B_STR  = 144;
static constexpr int B_QL   = 9216;
static constexpr int B_AG   = 18432;
static constexpr int B_AGL  = 36864;   // relative to B_AG
static constexpr int B_KT   = 92160;
static constexpr int B_KTL  = 33792;   // relative to B_KT
static constexpr int B_RS   = 159744;
static constexpr int B_SMEM = 160768;
static constexpr int KT_STR = 528;

__global__ __launch_bounds__(256)
void attn_out_kernel(const float* __restrict__ qkv,
                     const __nv_bfloat16* __restrict__ agh,
                     const __nv_bfloat16* __restrict__ agl,
                     const __nv_bfloat16* __restrict__ kth,
                     const __nv_bfloat16* __restrict__ ktl,
                     float* __restrict__ out)
{
    extern __shared__ char smem[];
    char* sc = smem;
    uint32_t sb = smem_to_u32(smem);
    int tid = threadIdx.x, lane = tid & 31, wid = tid >> 5;
    int qt = blockIdx.x, bh = blockIdx.y;
    int b = bh >> 3, h = bh & 7;
    int mw = wid & 1, nw = wid >> 1;
    int t8 = lane >> 3, rin = lane & 7;
    int a_row = rin + (t8 & 1) * 8, a_kb = (t8 >> 1) * 16;
    int b_row = (t8 >> 1) * 8 + rin, b_kb = (t8 & 1) * 16;

    // ---- async loads: agent (presplit), kv2t
    {
        const __nv_bfloat16* ah_p = agh + h * 16384;
        const __nv_bfloat16* al_p = agl + h * 16384;
        for (int i = tid; i < 2048; i += 256) {
            int r = i >> 3, c = i & 7;
            CP_ASYNC16(sb + B_AG + r * B_STR + c * 16,         ah_p + r * 64 + c * 8);
            CP_ASYNC16(sb + B_AG + B_AGL + r * B_STR + c * 16, al_p + r * 64 + c * 8);
        }
    }
    for (int c = tid; c < 2048; c += 256) {
        int r = c >> 5, c16 = c & 31;
        CP_ASYNC16(sb + B_KT + r * KT_STR + c16 * 16,         kth + bh * 16384 + r * 256 + c16 * 8);
        CP_ASYNC16(sb + B_KT + B_KTL + r * KT_STR + c16 * 16, ktl + bh * 16384 + r * 256 + c16 * 8);
    }
    CP_COMMIT();
    // ---- Q tile (scaled 0.125), scalar split
    {
        const float* qb = qkv + h * 64 + (long)(b * 8192 + qt * 64) * 1536;
        int lr = tid >> 2, lc = tid & 3;
#pragma unroll
        for (int g = 0; g < 4; ++g) {
            float4 v = *(const float4*)(qb + (long)lr * 1536 + lc * 16 + g * 4);
            v.x *= 0.125f; v.y *= 0.125f; v.z *= 0.125f; v.w *= 0.125f;
            uint32_t h01, h23, l01, l23;
            split2(v.x, v.y, h01, l01); split2(v.z, v.w, h23, l23);
            *(uint2*)(sc + lr * B_STR + lc * 32 + g * 8)        = make_uint2(h01, h23);
            *(uint2*)(sc + B_QL + lr * B_STR + lc * 32 + g * 8) = make_uint2(l01, l23);
        }
    }
    CP_WAIT0();
    __syncthreads();

    // ---- S = Q @ agent^T
    float s[2][8][4];
#pragma unroll
    for (int i = 0; i < 2; i++)
#pragma unroll
        for (int j = 0; j < 8; j++)
#pragma unroll
            for (int q = 0; q < 4; q++) s[i][j][q] = 0.f;

#pragma unroll
    for (int kf = 0; kf < 4; ++kf) {
        uint32_t ah[2][4], al[2][4];
#pragma unroll
        for (int mf = 0; mf < 2; ++mf) {
            uint32_t ad = sb + (mw * 32 + mf * 16 + a_row) * B_STR + kf * 32 + a_kb;
            LDMATRIX_X4(ah[mf][0], ah[mf][1], ah[mf][2], ah[mf][3], ad);
            LDMATRIX_X4(al[mf][0], al[mf][1], al[mf][2], al[mf][3], ad + B_QL);
        }
#pragma unroll
        for (int p = 0; p < 4; ++p) {
            uint32_t bhf[2][2], blf[2][2];
            uint32_t ad = sb + B_AG + (nw * 64 + p * 16 + b_row) * B_STR + kf * 32 + b_kb;
            LDMATRIX_X4(bhf[0][0], bhf[0][1], bhf[1][0], bhf[1][1], ad);
            LDMATRIX_X4(blf[0][0], blf[0][1], blf[1][0], blf[1][1], ad + B_AGL);
#pragma unroll
            for (int mf = 0; mf < 2; ++mf)
#pragma unroll
                for (int j = 0; j < 2; ++j) {
                    int nf = p * 2 + j;
                    MMA_BF16(s[mf][nf], ah[mf], bhf[j]);
                    MMA_BF16(s[mf][nf], ah[mf], blf[j]);
                    MMA_BF16(s[mf][nf], al[mf], bhf[j]);
                }
        }
    }

    // ---- exp, rowsums, P frags
    float* rsp = (float*)(sc + B_RS);
    uint32_t ph[2][4][4], pl[2][4][4];
#pragma unroll
    for (int mf = 0; mf < 2; ++mf) {
        float r0s = 0.f, r1s = 0.f;
#pragma unroll
        for (int nf = 0; nf < 8; ++nf) {
            s[mf][nf][0] = __expf(s[mf][nf][0]);
            s[mf][nf][1] = __expf(s[mf][nf][1]);
            s[mf][nf][2] = __expf(s[mf][nf][2]);
            s[mf][nf][3] = __expf(s[mf][nf][3]);
            r0s += s[mf][nf][0] + s[mf][nf][1];
            r1s += s[mf][nf][2] + s[mf][nf][3];
        }
        r0s += __shfl_xor_sync(0xffffffffu, r0s, 1);
        r0s += __shfl_xor_sync(0xffffffffu, r0s, 2);
        r1s += __shfl_xor_sync(0xffffffffu, r1s, 1);
        r1s += __shfl_xor_sync(0xffffffffu, r1s, 2);
        if ((lane & 3) == 0) {
            rsp[nw * 64 + mw * 32 + mf * 16 + (lane >> 2)]     = r0s;
            rsp[nw * 64 + mw * 32 + mf * 16 + (lane >> 2) + 8] = r1s;
        }
#pragma unroll
        for (int kt = 0; kt < 4; ++kt) {
            split2(s[mf][2 * kt][0],     s[mf][2 * kt][1],     ph[mf][kt][0], pl[mf][kt][0]);
            split2(s[mf][2 * kt][2],     s[mf][2 * kt][3],     ph[mf][kt][1], pl[mf][kt][1]);
            split2(s[mf][2 * kt + 1][0], s[mf][2 * kt + 1][1], ph[mf][kt][2], pl[mf][kt][2]);
            split2(s[mf][2 * kt + 1][2], s[mf][2 * kt + 1][3], ph[mf][kt][3], pl[mf][kt][3]);
        }
    }
    __syncthreads();

    // ---- O = P @ kv2t  (k = this warp's 64 agents)
    float o[2][8][4];
#pragma unroll
    for (int i = 0; i < 2; i++)
#pragma unroll
        for (int j = 0; j < 8; j++)
#pragma unroll
            for (int q = 0; q < 4; q++) o[i][j][q] = 0.f;

#pragma unroll
    for (int kt = 0; kt < 4; ++kt) {
#pragma unroll
        for (int p = 0; p < 4; ++p) {
            uint32_t bhf[2][2], blf[2][2];
            uint32_t ad = sb + B_KT + (p * 16 + b_row) * KT_STR + (nw * 64 + kt * 16) * 2 + b_kb;
            LDMATRIX_X4(bhf[0][0], bhf[0][1], bhf[1][0], bhf[1][1], ad);
            LDMATRIX_X4(blf[0][0], blf[0][1], blf[1][0], blf[1][1], ad + B_KTL);
#pragma unroll
            for (int mf = 0; mf < 2; ++mf)
#pragma unroll
                for (int j = 0; j < 2; ++j) {
                    int nf = p * 2 + j;
                    MMA_BF16(o[mf][nf], ph[mf][kt], bhf[j]);
                    MMA_BF16(o[mf][nf], ph[mf][kt], blf[j]);
                    MMA_BF16(o[mf][nf], pl[mf][kt], bhf[j]);
                }
        }
    }

    // ---- cross-warp-column reduction (reuse agent smem area)
    if (nw > 0) {
        char* pp = sc + B_AG + (nw - 1) * 16384;
#pragma unroll
        for (int mf = 0; mf < 2; ++mf)
#pragma unroll
            for (int nf = 0; nf < 8; ++nf) {
                int r0 = mw * 32 + mf * 16 + (lane >> 2);
                int c  = nf * 8 + (lane & 3) * 2;
                *(float2*)(pp + (r0 * 64 + c) * 4)       = make_float2(o[mf][nf][0], o[mf][nf][1]);
                *(float2*)(pp + ((r0 + 8) * 64 + c) * 4) = make_float2(o[mf][nf][2], o[mf][nf][3]);
            }
    }
    __syncthreads();

    if (nw == 0) {
#pragma unroll
        for (int mf = 0; mf < 2; ++mf) {
            int r0 = mw * 32 + mf * 16 + (lane >> 2);
            float inv0 = 1.f / (rsp[r0] + rsp[64 + r0] + rsp[128 + r0] + rsp[192 + r0]);
            float inv1 = 1.f / (rsp[r0 + 8] + rsp[64 + r0 + 8] + rsp[128 + r0 + 8] + rsp[192 + r0 + 8]);
#pragma unroll
            for (int nf = 0; nf < 8; ++nf) {
                int c = nf * 8 + (lane & 3) * 2;
                float v0 = o[mf][nf][0], v1 = o[mf][nf][1];
                float v2 = o[mf][nf][2], v3 = o[mf][nf][3];
#pragma unroll
                for (int i = 0; i < 3; ++i) {
                    char* pp = sc + B_AG + i * 16384;
                    float2 a0 = *(float2*)(pp + (r0 * 64 + c) * 4);
                    float2 a1 = *(float2*)(pp + ((r0 + 8) * 64 + c) * 4);
                    v0 += a0.x; v1 += a0.y; v2 += a1.x; v3 += a1.y;
                }
                long gr = (long)(b * 8192 + qt * 64 + r0) * 512 + h * 64 + c;
                *(float2*)(out + gr)             = make_float2(v0 * inv0, v1 * inv0);
                *(float2*)(out + gr + 8 * 512)   = make_float2(v2 * inv1, v3 * inv1);
            }
        }
    }
}

// ===========================================================================
extern "C" void kernel_launch(void* const* d_in, const int* in_sizes, int n_in,
                              void* d_out, int out_size)
{
    const float* x        = (const float*)d_in[0];
    const float* w_qkv    = (const float*)d_in[1];
    const float* agent    = (const float*)d_in[2];
    const float* w_noise  = (const float*)d_in[3];
    const float* b_noise  = (const float*)d_in[4];
    const float* w_mask   = (const float*)d_in[5];
    const float* b_mask   = (const float*)d_in[6];
    const float* w_thresh = (const float*)d_in[7];
    const float* b_thresh = (const float*)d_in[8];
    float* out = (float*)d_out;

    float *qkv, *kv, *ksum;
    __nv_bfloat16 *xh, *xl, *wh, *wl, *agh, *agl, *kth, *ktl;
    cudaGetSymbolAddress((void**)&qkv, g_qkv);
    cudaGetSymbolAddress((void**)&kv,  g_kv);
    cudaGetSymbolAddress((void**)&ksum, g_ksum);
    cudaGetSymbolAddress((void**)&xh,  g_xh);
    cudaGetSymbolAddress((void**)&xl,  g_xl);
    cudaGetSymbolAddress((void**)&wh,  g_wh);
    cudaGetSymbolAddress((void**)&wl,  g_wl);
    cudaGetSymbolAddress((void**)&agh, g_agh);
    cudaGetSymbolAddress((void**)&agl, g_agl);
    cudaGetSymbolAddress((void**)&kth, g_kt_h);
    cudaGetSymbolAddress((void**)&ktl, g_kt_l);

    cudaFuncSetAttribute(k1_mma_kernel,
                         cudaFuncAttributeMaxDynamicSharedMemorySize, K1_SMEM);
    cudaFuncSetAttribute(attn_kv_kernel,
                         cudaFuncAttributeMaxDynamicSharedMemorySize, A_SMEM);
    cudaFuncSetAttribute(attn_out_kernel,
                         cudaFuncAttributeMaxDynamicSharedMemorySize, B_SMEM);

    init_kernel<<<256, 256>>>();

    // 0) bf16 hi/lo splits
    split_bf16<<<1024, 256>>>(x, xh, xl, 16384L * 512);
    split_bf16<<<256, 256>>>(w_qkv, wh, wl, 1536L * 512);
    split_bf16<<<128, 256>>>(agent, agh, agl, 8L * 256 * 64);

    // 1) qkv = x @ w_qkv^T via bf16x3 mma.sync (64x64 warp tile)
    k1_mma_kernel<<<dim3(12, 128), 128, K1_SMEM>>>(xh, xl, wh, wl, qkv);

    // 2) fused: ka softmax-partials + kv accumulation
    attn_kv_kernel<<<dim3(8, 16), 256, A_SMEM>>>(qkv, agh, agl, kv, ksum);

    // 3) normalize kv
    kv_div_kernel<<<1024, 256>>>(kv, ksum);

    // 4) threshold scalar
    thresh_kernel<<<512, 256>>>(kv, w_thresh);

    // 5) mask/denoise + second softmax -> kv2 transposed bf16 hi/lo
    kv2_kernel<<<4096, 64>>>(kv, kth, ktl, w_noise, b_noise, w_mask, b_mask, b_thresh);

    // 6) fused: qa softmax + out = qa @ kv2
    attn_out_kernel<<<dim3(128, 16), 256, B_SMEM>>>(qkv, agh, agl, kth, ktl, out);
}

// round 12
// speedup vs baseline: 1.5386x; 1.5386x over previous
#include <cuda_runtime.h>
#include <cuda_bf16.h>
#include <math.h>
#include <cstdint>

// Problem constants: B=2, N=8192, DIM=512, H=8, A=256, D=64
__device__ float g_qkv[16384 * 1536];        // qkv scratch (fp32)
__device__ float g_kv [16 * 256 * 64];       // fused num -> normalized kv
__device__ float g_ksum[16 * 256];           // softmax denominators
__device__ float g_tsum;
// bf16 hi/lo split buffers
__device__ __align__(16) __nv_bfloat16 g_xh[16384 * 512];
__device__ __align__(16) __nv_bfloat16 g_xl[16384 * 512];
__device__ __align__(16) __nv_bfloat16 g_wh[1536 * 512];
__device__ __align__(16) __nv_bfloat16 g_wl[1536 * 512];
__device__ __align__(16) __nv_bfloat16 g_agh[8 * 256 * 64];
__device__ __align__(16) __nv_bfloat16 g_agl[8 * 256 * 64];
// kv2 transposed [bh][d][a], bf16 hi/lo
__device__ __align__(16) __nv_bfloat16 g_kt_h[16 * 64 * 256];
__device__ __align__(16) __nv_bfloat16 g_kt_l[16 * 64 * 256];

// ===========================================================================
// PTX helpers
// ===========================================================================
__device__ __forceinline__ uint32_t smem_to_u32(const void* p) {
    uint32_t a;
    asm("{ .reg .u64 t; cvta.to.shared.u64 t, %1; cvt.u32.u64 %0, t; }" : "=r"(a) : "l"(p));
    return a;
}
#define LDMATRIX_X4(r0, r1, r2, r3, addr) \
    asm volatile("ldmatrix.sync.aligned.m8n8.x4.shared.b16 {%0,%1,%2,%3}, [%4];" \
                 : "=r"(r0), "=r"(r1), "=r"(r2), "=r"(r3) : "r"(addr))
#define LDMATRIX_X4_T(r0, r1, r2, r3, addr) \
    asm volatile("ldmatrix.sync.aligned.m8n8.x4.trans.shared.b16 {%0,%1,%2,%3}, [%4];" \
                 : "=r"(r0), "=r"(r1), "=r"(r2), "=r"(r3) : "r"(addr))
#define MMA_BF16(c, a, b) \
    asm volatile("mma.sync.aligned.m16n8k16.row.col.f32.bf16.bf16.f32 " \
                 "{%0,%1,%2,%3}, {%4,%5,%6,%7}, {%8,%9}, {%0,%1,%2,%3};" \
                 : "+f"((c)[0]), "+f"((c)[1]), "+f"((c)[2]), "+f"((c)[3]) \
                 : "r"((a)[0]), "r"((a)[1]), "r"((a)[2]), "r"((a)[3]), \
                   "r"((b)[0]), "r"((b)[1]))
#define CP_ASYNC16(dst, src) \
    asm volatile("cp.async.cg.shared.global [%0], [%1], 16;" :: "r"(dst), "l"(src))
#define CP_COMMIT() asm volatile("cp.async.commit_group;" ::: "memory")
#define CP_WAIT0()  asm volatile("cp.async.wait_group 0;" ::: "memory")

// pack two floats -> bf16x2 hi word and residual lo word
__device__ __forceinline__ void split2(float a, float b, uint32_t& h, uint32_t& l) {
    __nv_bfloat16 ha = __float2bfloat16_rn(a), hb = __float2bfloat16_rn(b);
    __nv_bfloat162 hp; hp.x = ha; hp.y = hb;
    __nv_bfloat162 lp;
    lp.x = __float2bfloat16_rn(a - __bfloat162float(ha));
    lp.y = __float2bfloat16_rn(b - __bfloat162float(hb));
    h = *(uint32_t*)&hp; l = *(uint32_t*)&lp;
}

// ===========================================================================
// bf16 split kernel
// ===========================================================================
__global__ __launch_bounds__(256)
void split_bf16(const float* __restrict__ in, __nv_bfloat16* __restrict__ hi,
                __nv_bfloat16* __restrict__ lo, long n) {
    for (long i = ((long)blockIdx.x * blockDim.x + threadIdx.x) * 4; i < n;
         i += (long)gridDim.x * blockDim.x * 4) {
        float4 v = *(const float4*)(in + i);
        uint32_t h01, h23, l01, l23;
        split2(v.x, v.y, h01, l01);
        split2(v.z, v.w, h23, l23);
        *(uint2*)(hi + i) = make_uint2(h01, h23);
        *(uint2*)(lo + i) = make_uint2(l01, l23);
    }
}

// ===========================================================================
// K1: C[16384,1536] = X[16384,512] @ W[1536,512]^T via bf16x3 mma.sync.
// VERIFIED round-6 config: CTA 128x128, 8 warps (2m x 4n), warp tile 64x32.
// (4-warp 64x64 retile regressed: latency/occupancy-bound, not smem-bound.)
// ===========================================================================
static constexpr int K1_ROWB = 80;
static constexpr int K1_BUF  = 128 * K1_ROWB;
static constexpr int K1_STAGE = 4 * K1_BUF;
static constexpr int K1_SMEM  = 2 * K1_STAGE;

__global__ __launch_bounds__(256)
void k1_mma_kernel(const __nv_bfloat16* __restrict__ xh,
                   const __nv_bfloat16* __restrict__ xl,
                   const __nv_bfloat16* __restrict__ wh,
                   const __nv_bfloat16* __restrict__ wl,
                   float* __restrict__ C)
{
    extern __shared__ char smem[];
    uint32_t sb = smem_to_u32(smem);
    int tid = threadIdx.x;
    int lane = tid & 31, wid = tid >> 5;
    int mw = wid & 1, nw = wid >> 1;          // warp grid 2m x 4n
    int nt = blockIdx.x, mt = blockIdx.y;

    const __nv_bfloat16* srcA_h = xh + (long)(mt * 128) * 512;
    const __nv_bfloat16* srcA_l = xl + (long)(mt * 128) * 512;
    const __nv_bfloat16* srcB_h = wh + (long)(nt * 128) * 512;
    const __nv_bfloat16* srcB_l = wl + (long)(nt * 128) * 512;

    float acc[4][4][4];
#pragma unroll
    for (int i = 0; i < 4; i++)
#pragma unroll
        for (int j = 0; j < 4; j++)
#pragma unroll
            for (int q = 0; q < 4; q++) acc[i][j][q] = 0.f;

    int a_tile = lane >> 3, a_rin = lane & 7;
    int a_row = a_rin + (a_tile & 1) * 8;
    int a_kb  = (a_tile >> 1) * 16;
    int b_row = (a_tile >> 1) * 8 + a_rin;
    int b_kb  = (a_tile & 1) * 16;

    auto issue_loads = [&](int stage, int k0) {
        uint32_t base = sb + stage * K1_STAGE;
#pragma unroll
        for (int j = 0; j < 8; j++) {
            int idx = tid + j * 256;
            int buf = idx >> 9;
            int r   = (idx >> 2) & 127;
            int g   = idx & 3;
            const __nv_bfloat16* src =
                (buf == 0 ? srcA_h : buf == 1 ? srcA_l : buf == 2 ? srcB_h : srcB_l)
                + (long)r * 512 + k0 + g * 8;
            uint32_t dst = base + buf * K1_BUF + r * K1_ROWB + g * 16;
            CP_ASYNC16(dst, src);
        }
    };

    issue_loads(0, 0);
    CP_COMMIT(); CP_WAIT0();
    __syncthreads();

    for (int kc = 0; kc < 16; ++kc) {
        int cur = kc & 1;
        if (kc < 15) { issue_loads(cur ^ 1, (kc + 1) * 32); CP_COMMIT(); }

        uint32_t st = sb + cur * K1_STAGE;
        uint32_t Ah = st,              Al = st + K1_BUF;
        uint32_t Bh = st + 2 * K1_BUF, Bl = st + 3 * K1_BUF;

#pragma unroll
        for (int s = 0; s < 2; ++s) {
            int skb = s * 32;
            uint32_t ah[4][4], al[4][4], bh[4][2], bl[4][2];
#pragma unroll
            for (int mf = 0; mf < 4; mf++) {
                uint32_t addr = Ah + (mw * 64 + mf * 16 + a_row) * K1_ROWB + skb + a_kb;
                LDMATRIX_X4(ah[mf][0], ah[mf][1], ah[mf][2], ah[mf][3], addr);
            }
#pragma unroll
            for (int p = 0; p < 2; p++) {
                uint32_t addr = Bh + (nw * 32 + p * 16 + b_row) * K1_ROWB + skb + b_kb;
                LDMATRIX_X4(bh[p * 2][0], bh[p * 2][1], bh[p * 2 + 1][0], bh[p * 2 + 1][1], addr);
                uint32_t addr2 = Bl + (nw * 32 + p * 16 + b_row) * K1_ROWB + skb + b_kb;
                LDMATRIX_X4(bl[p * 2][0], bl[p * 2][1], bl[p * 2 + 1][0], bl[p * 2 + 1][1], addr2);
            }
#pragma unroll
            for (int mf = 0; mf < 4; mf++)
#pragma unroll
                for (int nf = 0; nf < 4; nf++) MMA_BF16(acc[mf][nf], ah[mf], bh[nf]);
#pragma unroll
            for (int mf = 0; mf < 4; mf++)
#pragma unroll
                for (int nf = 0; nf < 4; nf++) MMA_BF16(acc[mf][nf], ah[mf], bl[nf]);
#pragma unroll
            for (int mf = 0; mf < 4; mf++) {
                uint32_t addr = Al + (mw * 64 + mf * 16 + a_row) * K1_ROWB + skb + a_kb;
                LDMATRIX_X4(al[mf][0], al[mf][1], al[mf][2], al[mf][3], addr);
            }
#pragma unroll
            for (int mf = 0; mf < 4; mf++)
#pragma unroll
                for (int nf = 0; nf < 4; nf++) MMA_BF16(acc[mf][nf], al[mf], bh[nf]);
        }

        if (kc < 15) CP_WAIT0();
        __syncthreads();
    }

    int rbase = mt * 128 + mw * 64 + (lane >> 2);
    int cbase = nt * 128 + nw * 32 + (lane & 3) * 2;
#pragma unroll
    for (int mf = 0; mf < 4; mf++)
#pragma unroll
        for (int nf = 0; nf < 4; nf++) {
            long r0 = rbase + mf * 16;
            long cc = cbase + nf * 8;
            *(float2*)(C + r0 * 1536 + cc)       = make_float2(acc[mf][nf][0], acc[mf][nf][1]);
            *(float2*)(C + (r0 + 8) * 1536 + cc) = make_float2(acc[mf][nf][2], acc[mf][nf][3]);
        }
}

// ===========================================================================
// init: zero atomic accumulators
// ===========================================================================
__global__ void init_kernel() {
    int i = blockIdx.x * blockDim.x + threadIdx.x;
    if (i == 0) g_tsum = 0.f;
    if (i < 16 * 256) g_ksum[i] = 0.f;
    for (; i < 16 * 256 * 64; i += gridDim.x * blockDim.x) g_kv[i] = 0.f;
}

// ===========================================================================
// Fused stage A: kv-partials (S = agent@K^T, P=exp, num+=P@V, den+=rowsum)
// grid (16, 16), 256 threads: 16 n-splits x 512 tokens -> full-chip coverage.
// ===========================================================================
static constexpr int A_STR   = 144;
static constexpr int A_AGL   = 36864;
static constexpr int A_KH    = 73728;
static constexpr int A_KL    = A_KH + 4608;
static constexpr int A_VH    = A_KH + 9216;
static constexpr int A_VL    = A_KH + 13824;
static constexpr int A_SMEM  = 92160;

__global__ __launch_bounds__(256)
void attn_kv_kernel(const float* __restrict__ qkv,
                    const __nv_bfloat16* __restrict__ agh,
                    const __nv_bfloat16* __restrict__ agl,
                    float* __restrict__ kv, float* __restrict__ ksum)
{
    extern __shared__ char smem[];
    char* sc = smem;
    uint32_t sb = smem_to_u32(smem);
    int tid = threadIdx.x, lane = tid & 31, wid = tid >> 5;
    int split = blockIdx.x, bh = blockIdx.y;
    int b = bh >> 3, h = bh & 7;
    int t8 = lane >> 3, rin = lane & 7;
    int a_row = rin + (t8 & 1) * 8, a_kb = (t8 >> 1) * 16;
    int b_row = (t8 >> 1) * 8 + rin, b_kb = (t8 & 1) * 16;
    int v_row = (t8 & 1) * 8 + rin, v_cb = (t8 >> 1) * 16;

    // ---- agent hi/lo via cp.async (presplit)
    {
        const __nv_bfloat16* ah_p = agh + h * 16384;
        const __nv_bfloat16* al_p = agl + h * 16384;
        for (int i = tid; i < 2048; i += 256) {
            int r = i >> 3, c = i & 7;
            CP_ASYNC16(sb + r * A_STR + c * 16,         ah_p + r * 64 + c * 8);
            CP_ASYNC16(sb + A_AGL + r * A_STR + c * 16, al_p + r * 64 + c * 8);
        }
        CP_COMMIT();
    }

    float kvacc[2][8][4];
#pragma unroll
    for (int i = 0; i < 2; i++)
#pragma unroll
        for (int j = 0; j < 8; j++)
#pragma unroll
            for (int q = 0; q < 4; q++) kvacc[i][j][q] = 0.f;
    float rs[2][2] = {{0.f, 0.f}, {0.f, 0.f}};

    const float* kbase = qkv + 512 + h * 64 + (long)(b * 8192 + split * 512) * 1536;
    int lr = tid >> 3, lc = tid & 7;

    float4 pk0, pk1, pv0, pv1;
    {
        const float* kr = kbase + (long)lr * 1536 + lc * 8;
        pk0 = *(const float4*)kr;         pk1 = *(const float4*)(kr + 4);
        pv0 = *(const float4*)(kr + 512); pv1 = *(const float4*)(kr + 516);
    }
    CP_WAIT0();
    __syncthreads();

    for (int t = 0; t < 16; ++t) {
        {
            uint32_t x0, x1, x2, x3, y0, y1, y2, y3;
            split2(pk0.x, pk0.y, x0, y0); split2(pk0.z, pk0.w, x1, y1);
            split2(pk1.x, pk1.y, x2, y2); split2(pk1.z, pk1.w, x3, y3);
            *(uint4*)(sc + A_KH + lr * A_STR + lc * 16) = make_uint4(x0, x1, x2, x3);
            *(uint4*)(sc + A_KL + lr * A_STR + lc * 16) = make_uint4(y0, y1, y2, y3);
            split2(pv0.x, pv0.y, x0, y0); split2(pv0.z, pv0.w, x1, y1);
            split2(pv1.x, pv1.y, x2, y2); split2(pv1.z, pv1.w, x3, y3);
            *(uint4*)(sc + A_VH + lr * A_STR + lc * 16) = make_uint4(x0, x1, x2, x3);
            *(uint4*)(sc + A_VL + lr * A_STR + lc * 16) = make_uint4(y0, y1, y2, y3);
        }
        __syncthreads();
        if (t < 15) {
            const float* kr = kbase + (long)((t + 1) * 32 + lr) * 1536 + lc * 8;
            pk0 = *(const float4*)kr;         pk1 = *(const float4*)(kr + 4);
            pv0 = *(const float4*)(kr + 512); pv1 = *(const float4*)(kr + 516);
        }

        float s[2][4][4];
#pragma unroll
        for (int i = 0; i < 2; i++)
#pragma unroll
            for (int j = 0; j < 4; j++)
#pragma unroll
                for (int q = 0; q < 4; q++) s[i][j][q] = 0.f;

#pragma unroll
        for (int kf = 0; kf < 4; ++kf) {
            uint32_t ah[2][4], al[2][4];
#pragma unroll
            for (int mf = 0; mf < 2; ++mf) {
                uint32_t ad = sb + (wid * 32 + mf * 16 + a_row) * A_STR + kf * 32 + a_kb;
                LDMATRIX_X4(ah[mf][0], ah[mf][1], ah[mf][2], ah[mf][3], ad);
                LDMATRIX_X4(al[mf][0], al[mf][1], al[mf][2], al[mf][3], ad + A_AGL);
            }
            uint32_t kbh[4][2], kbl[4][2];
#pragma unroll
            for (int p = 0; p < 2; ++p) {
                uint32_t ad = sb + A_KH + (p * 16 + b_row) * A_STR + kf * 32 + b_kb;
                LDMATRIX_X4(kbh[p * 2][0], kbh[p * 2][1], kbh[p * 2 + 1][0], kbh[p * 2 + 1][1], ad);
                LDMATRIX_X4(kbl[p * 2][0], kbl[p * 2][1], kbl[p * 2 + 1][0], kbl[p * 2 + 1][1], ad + 4608);
            }
#pragma unroll
            for (int mf = 0; mf < 2; ++mf)
#pragma unroll
                for (int nf = 0; nf < 4; ++nf) {
                    MMA_BF16(s[mf][nf], ah[mf], kbh[nf]);
                    MMA_BF16(s[mf][nf], ah[mf], kbl[nf]);
                    MMA_BF16(s[mf][nf], al[mf], kbh[nf]);
                }
        }

        uint32_t ph[2][2][4], pl[2][2][4];
#pragma unroll
        for (int mf = 0; mf < 2; ++mf) {
#pragma unroll
            for (int nf = 0; nf < 4; ++nf) {
                s[mf][nf][0] = __expf(s[mf][nf][0]);
                s[mf][nf][1] = __expf(s[mf][nf][1]);
                s[mf][nf][2] = __expf(s[mf][nf][2]);
                s[mf][nf][3] = __expf(s[mf][nf][3]);
                rs[mf][0] += s[mf][nf][0] + s[mf][nf][1];
                rs[mf][1] += s[mf][nf][2] + s[mf][nf][3];
            }
#pragma unroll
            for (int kt = 0; kt < 2; ++kt) {
                split2(s[mf][2 * kt][0],     s[mf][2 * kt][1],     ph[mf][kt][0], pl[mf][kt][0]);
                split2(s[mf][2 * kt][2],     s[mf][2 * kt][3],     ph[mf][kt][1], pl[mf][kt][1]);
                split2(s[mf][2 * kt + 1][0], s[mf][2 * kt + 1][1], ph[mf][kt][2], pl[mf][kt][2]);
                split2(s[mf][2 * kt + 1][2], s[mf][2 * kt + 1][3], ph[mf][kt][3], pl[mf][kt][3]);
            }
        }

#pragma unroll
        for (int kt = 0; kt < 2; ++kt) {
#pragma unroll
            for (int p = 0; p < 4; ++p) {
                uint32_t bvh[2][2], bvl[2][2];
                uint32_t ad = sb + A_VH + (kt * 16 + v_row) * A_STR + p * 32 + v_cb;
                LDMATRIX_X4_T(bvh[0][0], bvh[0][1], bvh[1][0], bvh[1][1], ad);
                LDMATRIX_X4_T(bvl[0][0], bvl[0][1], bvl[1][0], bvl[1][1], ad + 4608);
#pragma unroll
                for (int mf = 0; mf < 2; ++mf)
#pragma unroll
                    for (int j = 0; j < 2; ++j) {
                        int nf = p * 2 + j;
                        MMA_BF16(kvacc[mf][nf], ph[mf][kt], bvh[j]);
                        MMA_BF16(kvacc[mf][nf], ph[mf][kt], bvl[j]);
                        MMA_BF16(kvacc[mf][nf], pl[mf][kt], bvh[j]);
                    }
            }
        }
        __syncthreads();
    }

#pragma unroll
    for (int mf = 0; mf < 2; ++mf)
#pragma unroll
        for (int j = 0; j < 2; ++j) {
            float r = rs[mf][j];
            r += __shfl_xor_sync(0xffffffffu, r, 1);
            r += __shfl_xor_sync(0xffffffffu, r, 2);
            if ((lane & 3) == 0)
                atomicAdd(&ksum[bh * 256 + wid * 32 + mf * 16 + j * 8 + (lane >> 2)], r);
        }
    float* kvb = kv + bh * 16384;
#pragma unroll
    for (int mf = 0; mf < 2; ++mf)
#pragma unroll
        for (int nf = 0; nf < 8; ++nf) {
            int r0 = wid * 32 + mf * 16 + (lane >> 2);
            int c  = nf * 8 + (lane & 3) * 2;
            atomicAdd(&kvb[r0 * 64 + c],           kvacc[mf][nf][0]);
            atomicAdd(&kvb[r0 * 64 + c + 1],       kvacc[mf][nf][1]);
            atomicAdd(&kvb[(r0 + 8) * 64 + c],     kvacc[mf][nf][2]);
            atomicAdd(&kvb[(r0 + 8) * 64 + c + 1], kvacc[mf][nf][3]);
        }
}

// kv /= ksum
__global__ __launch_bounds__(256)
void kv_div_kernel(float* __restrict__ kv, const float* __restrict__ ksum) {
    int i = blockIdx.x * 256 + threadIdx.x;
    kv[i] = kv[i] / ksum[i >> 6];
}

// thresh: tsum = sum_i kv_flat[i] * w_thresh[i % 512]
__global__ __launch_bounds__(256)
void thresh_kernel(const float* __restrict__ kv, const float* __restrict__ wth)
{
    __shared__ float red[256];
    float s = 0.f;
    for (long i = blockIdx.x * 256 + threadIdx.x; i < 16L * 256 * 64;
         i += (long)gridDim.x * 256) {
        s += kv[i] * wth[i & 511];
    }
    red[threadIdx.x] = s; __syncthreads();
    for (int st = 128; st > 0; st >>= 1) {
        if (threadIdx.x < st) red[threadIdx.x] += red[threadIdx.x + st];
        __syncthreads();
    }
    if (threadIdx.x == 0) atomicAdd(&g_tsum, red[0]);
}

__device__ __forceinline__ float sigmoidf_(float x) { return 1.f / (1.f + expf(-x)); }

// ===========================================================================
// kv2 = softmax_d(kv*mask + denoise); write TRANSPOSED bf16 hi/lo [bh][d][a]
// ===========================================================================
__global__ __launch_bounds__(64)
void kv2_kernel(const float* __restrict__ kv,
                __nv_bfloat16* __restrict__ kth, __nv_bfloat16* __restrict__ ktl,
                const float* __restrict__ wn, const float* __restrict__ bn,
                const float* __restrict__ wm, const float* __restrict__ bm,
                const float* __restrict__ bth)
{
    long r = blockIdx.x;
    int bh = (int)(r >> 8), a = (int)(r & 255);
    int d = threadIdx.x;
    __shared__ float kr[64];
    __shared__ float tmp[64];

    kr[d] = kv[r * 64 + d];
    __syncthreads();

    float thresh = sigmoidf_(g_tsum * (1.f / 512.f) + bth[0]);

    float sn = bn[d], sm = bm[d];
#pragma unroll 8
    for (int e = 0; e < 64; e++) {
        float ke = kr[e];
        sn += ke * wn[d * 64 + e];
        sm += ke * wm[d * 64 + e];
    }
    float denoise = sigmoidf_(sn);
    float mval    = sigmoidf_(sm);
    float mbin    = (mval > thresh) ? 1.f : 0.f;
    float val     = kr[d] * mbin + denoise;

    tmp[d] = val; __syncthreads();
    float mx = -3.4e38f;
    for (int e = 0; e < 64; e++) mx = fmaxf(mx, tmp[e]);
    __syncthreads();
    float ev = expf(val - mx);
    tmp[d] = ev; __syncthreads();
    float sum = 0.f;
    for (int e = 0; e < 64; e++) sum += tmp[e];
    float v = ev / sum;
    __nv_bfloat16 hh = __float2bfloat16_rn(v);
    kth[bh * 16384 + d * 256 + a] = hh;
    ktl[bh * 16384 + d * 256 + a] = __float2bfloat16_rn(v - __bfloat162float(hh));
}

// ===========================================================================
// Fused stage B: L=(q/8)@agent^T, P=exp(L), O=P@kv2^T, out=O/rowsum
// grid (128, 16), 256 threads.
// ===========================================================================
static constexpr int B_STR  = 144;
static constexpr int B_QL   = 9216;
static constexpr int B_AG   = 18432;
static constexpr int B_AGL  = 36864;   // relative to B_AG
static constexpr int B_KT   = 92160;
static constexpr int B_KTL  = 33792;   // relative to B_KT
static constexpr int B_RS   = 159744;
static constexpr int B_SMEM = 160768;
static constexpr int KT_STR = 528;

__global__ __launch_bounds__(256)
void attn_out_kernel(const float* __restrict__ qkv,
                     const __nv_bfloat16* __restrict__ agh,
                     const __nv_bfloat16* __restrict__ agl,
                     const __nv_bfloat16* __restrict__ kth,
                     const __nv_bfloat16* __restrict__ ktl,
                     float* __restrict__ out)
{
    extern __shared__ char smem[];
    char* sc = smem;
    uint32_t sb = smem_to_u32(smem);
    int tid = threadIdx.x, lane = tid & 31, wid = tid >> 5;
    int qt = blockIdx.x, bh = blockIdx.y;
    int b = bh >> 3, h = bh & 7;
    int mw = wid & 1, nw = wid >> 1;
    int t8 = lane >> 3, rin = lane & 7;
    int a_row = rin + (t8 & 1) * 8, a_kb = (t8 >> 1) * 16;
    int b_row = (t8 >> 1) * 8 + rin, b_kb = (t8 & 1) * 16;

    // ---- async loads: agent (presplit), kv2t
    {
        const __nv_bfloat16* ah_p = agh + h * 16384;
        const __nv_bfloat16* al_p = agl + h * 16384;
        for (int i = tid; i < 2048; i += 256) {
            int r = i >> 3, c = i & 7;
            CP_ASYNC16(sb + B_AG + r * B_STR + c * 16,         ah_p + r * 64 + c * 8);
            CP_ASYNC16(sb + B_AG + B_AGL + r * B_STR + c * 16, al_p + r * 64 + c * 8);
        }
    }
    for (int c = tid; c < 2048; c += 256) {
        int r = c >> 5, c16 = c & 31;
        CP_ASYNC16(sb + B_KT + r * KT_STR + c16 * 16,         kth + bh * 16384 + r * 256 + c16 * 8);
        CP_ASYNC16(sb + B_KT + B_KTL + r * KT_STR + c16 * 16, ktl + bh * 16384 + r * 256 + c16 * 8);
    }
    CP_COMMIT();
    // ---- Q tile (scaled 0.125), scalar split
    {
        const float* qb = qkv + h * 64 + (long)(b * 8192 + qt * 64) * 1536;
        int lr = tid >> 2, lc = tid & 3;
#pragma unroll
        for (int g = 0; g < 4; ++g) {
            float4 v = *(const float4*)(qb + (long)lr * 1536 + lc * 16 + g * 4);
            v.x *= 0.125f; v.y *= 0.125f; v.z *= 0.125f; v.w *= 0.125f;
            uint32_t h01, h23, l01, l23;
            split2(v.x, v.y, h01, l01); split2(v.z, v.w, h23, l23);
            *(uint2*)(sc + lr * B_STR + lc * 32 + g * 8)        = make_uint2(h01, h23);
            *(uint2*)(sc + B_QL + lr * B_STR + lc * 32 + g * 8) = make_uint2(l01, l23);
        }
    }
    CP_WAIT0();
    __syncthreads();

    // ---- S = Q @ agent^T
    float s[2][8][4];
#pragma unroll
    for (int i = 0; i < 2; i++)
#pragma unroll
        for (int j = 0; j < 8; j++)
#pragma unroll
            for (int q = 0; q < 4; q++) s[i][j][q] = 0.f;

#pragma unroll
    for (int kf = 0; kf < 4; ++kf) {
        uint32_t ah[2][4], al[2][4];
#pragma unroll
        for (int mf = 0; mf < 2; ++mf) {
            uint32_t ad = sb + (mw * 32 + mf * 16 + a_row) * B_STR + kf * 32 + a_kb;
            LDMATRIX_X4(ah[mf][0], ah[mf][1], ah[mf][2], ah[mf][3], ad);
            LDMATRIX_X4(al[mf][0], al[mf][1], al[mf][2], al[mf][3], ad + B_QL);
        }
#pragma unroll
        for (int p = 0; p < 4; ++p) {
            uint32_t bhf[2][2], blf[2][2];
            uint32_t ad = sb + B_AG + (nw * 64 + p * 16 + b_row) * B_STR + kf * 32 + b_kb;
            LDMATRIX_X4(bhf[0][0], bhf[0][1], bhf[1][0], bhf[1][1], ad);
            LDMATRIX_X4(blf[0][0], blf[0][1], blf[1][0], blf[1][1], ad + B_AGL);
#pragma unroll
            for (int mf = 0; mf < 2; ++mf)
#pragma unroll
                for (int j = 0; j < 2; ++j) {
                    int nf = p * 2 + j;
                    MMA_BF16(s[mf][nf], ah[mf], bhf[j]);
                    MMA_BF16(s[mf][nf], ah[mf], blf[j]);
                    MMA_BF16(s[mf][nf], al[mf], bhf[j]);
                }
        }
    }

    // ---- exp, rowsums, P frags
    float* rsp = (float*)(sc + B_RS);
    uint32_t ph[2][4][4], pl[2][4][4];
#pragma unroll
    for (int mf = 0; mf < 2; ++mf) {
        float r0s = 0.f, r1s = 0.f;
#pragma unroll
        for (int nf = 0; nf < 8; ++nf) {
            s[mf][nf][0] = __expf(s[mf][nf][0]);
            s[mf][nf][1] = __expf(s[mf][nf][1]);
            s[mf][nf][2] = __expf(s[mf][nf][2]);
            s[mf][nf][3] = __expf(s[mf][nf][3]);
            r0s += s[mf][nf][0] + s[mf][nf][1];
            r1s += s[mf][nf][2] + s[mf][nf][3];
        }
        r0s += __shfl_xor_sync(0xffffffffu, r0s, 1);
        r0s += __shfl_xor_sync(0xffffffffu, r0s, 2);
        r1s += __shfl_xor_sync(0xffffffffu, r1s, 1);
        r1s += __shfl_xor_sync(0xffffffffu, r1s, 2);
        if ((lane & 3) == 0) {
            rsp[nw * 64 + mw * 32 + mf * 16 + (lane >> 2)]     = r0s;
            rsp[nw * 64 + mw * 32 + mf * 16 + (lane >> 2) + 8] = r1s;
        }
#pragma unroll
        for (int kt = 0; kt < 4; ++kt) {
            split2(s[mf][2 * kt][0],     s[mf][2 * kt][1],     ph[mf][kt][0], pl[mf][kt][0]);
            split2(s[mf][2 * kt][2],     s[mf][2 * kt][3],     ph[mf][kt][1], pl[mf][kt][1]);
            split2(s[mf][2 * kt + 1][0], s[mf][2 * kt + 1][1], ph[mf][kt][2], pl[mf][kt][2]);
            split2(s[mf][2 * kt + 1][2], s[mf][2 * kt + 1][3], ph[mf][kt][3], pl[mf][kt][3]);
        }
    }
    __syncthreads();

    // ---- O = P @ kv2t  (k = this warp's 64 agents)
    float o[2][8][4];
#pragma unroll
    for (int i = 0; i < 2; i++)
#pragma unroll
        for (int j = 0; j < 8; j++)
#pragma unroll
            for (int q = 0; q < 4; q++) o[i][j][q] = 0.f;

#pragma unroll
    for (int kt = 0; kt < 4; ++kt) {
#pragma unroll
        for (int p = 0; p < 4; ++p) {
            uint32_t bhf[2][2], blf[2][2];
            uint32_t ad = sb + B_KT + (p * 16 + b_row) * KT_STR + (nw * 64 + kt * 16) * 2 + b_kb;
            LDMATRIX_X4(bhf[0][0], bhf[0][1], bhf[1][0], bhf[1][1], ad);
            LDMATRIX_X4(blf[0][0], blf[0][1], blf[1][0], blf[1][1], ad + B_KTL);
#pragma unroll
            for (int mf = 0; mf < 2; ++mf)
#pragma unroll
                for (int j = 0; j < 2; ++j) {
                    int nf = p * 2 + j;
                    MMA_BF16(o[mf][nf], ph[mf][kt], bhf[j]);
                    MMA_BF16(o[mf][nf], ph[mf][kt], blf[j]);
                    MMA_BF16(o[mf][nf], pl[mf][kt], bhf[j]);
                }
        }
    }

    // ---- cross-warp-column reduction (reuse agent smem area)
    if (nw > 0) {
        char* pp = sc + B_AG + (nw - 1) * 16384;
#pragma unroll
        for (int mf = 0; mf < 2; ++mf)
#pragma unroll
            for (int nf = 0; nf < 8; ++nf) {
                int r0 = mw * 32 + mf * 16 + (lane >> 2);
                int c  = nf * 8 + (lane & 3) * 2;
                *(float2*)(pp + (r0 * 64 + c) * 4)       = make_float2(o[mf][nf][0], o[mf][nf][1]);
                *(float2*)(pp + ((r0 + 8) * 64 + c) * 4) = make_float2(o[mf][nf][2], o[mf][nf][3]);
            }
    }
    __syncthreads();

    if (nw == 0) {
#pragma unroll
        for (int mf = 0; mf < 2; ++mf) {
            int r0 = mw * 32 + mf * 16 + (lane >> 2);
            float inv0 = 1.f / (rsp[r0] + rsp[64 + r0] + rsp[128 + r0] + rsp[192 + r0]);
            float inv1 = 1.f / (rsp[r0 + 8] + rsp[64 + r0 + 8] + rsp[128 + r0 + 8] + rsp[192 + r0 + 8]);
#pragma unroll
            for (int nf = 0; nf < 8; ++nf) {
                int c = nf * 8 + (lane & 3) * 2;
                float v0 = o[mf][nf][0], v1 = o[mf][nf][1];
                float v2 = o[mf][nf][2], v3 = o[mf][nf][3];
#pragma unroll
                for (int i = 0; i < 3; ++i) {
                    char* pp = sc + B_AG + i * 16384;
                    float2 a0 = *(float2*)(pp + (r0 * 64 + c) * 4);
                    float2 a1 = *(float2*)(pp + ((r0 + 8) * 64 + c) * 4);
                    v0 += a0.x; v1 += a0.y; v2 += a1.x; v3 += a1.y;
                }
                long gr = (long)(b * 8192 + qt * 64 + r0) * 512 + h * 64 + c;
                *(float2*)(out + gr)             = make_float2(v0 * inv0, v1 * inv0);
                *(float2*)(out + gr + 8 * 512)   = make_float2(v2 * inv1, v3 * inv1);
            }
        }
    }
}

// ===========================================================================
extern "C" void kernel_launch(void* const* d_in, const int* in_sizes, int n_in,
                              void* d_out, int out_size)
{
    const float* x        = (const float*)d_in[0];
    const float* w_qkv    = (const float*)d_in[1];
    const float* agent    = (const float*)d_in[2];
    const float* w_noise  = (const float*)d_in[3];
    const float* b_noise  = (const float*)d_in[4];
    const float* w_mask   = (const float*)d_in[5];
    const float* b_mask   = (const float*)d_in[6];
    const float* w_thresh = (const float*)d_in[7];
    const float* b_thresh = (const float*)d_in[8];
    float* out = (float*)d_out;

    float *qkv, *kv, *ksum;
    __nv_bfloat16 *xh, *xl, *wh, *wl, *agh, *agl, *kth, *ktl;
    cudaGetSymbolAddress((void**)&qkv, g_qkv);
    cudaGetSymbolAddress((void**)&kv,  g_kv);
    cudaGetSymbolAddress((void**)&ksum, g_ksum);
    cudaGetSymbolAddress((void**)&xh,  g_xh);
    cudaGetSymbolAddress((void**)&xl,  g_xl);
    cudaGetSymbolAddress((void**)&wh,  g_wh);
    cudaGetSymbolAddress((void**)&wl,  g_wl);
    cudaGetSymbolAddress((void**)&agh, g_agh);
    cudaGetSymbolAddress((void**)&agl, g_agl);
    cudaGetSymbolAddress((void**)&kth, g_kt_h);
    cudaGetSymbolAddress((void**)&ktl, g_kt_l);

    cudaFuncSetAttribute(k1_mma_kernel,
                         cudaFuncAttributeMaxDynamicSharedMemorySize, K1_SMEM);
    cudaFuncSetAttribute(attn_kv_kernel,
                         cudaFuncAttributeMaxDynamicSharedMemorySize, A_SMEM);
    cudaFuncSetAttribute(attn_out_kernel,
                         cudaFuncAttributeMaxDynamicSharedMemorySize, B_SMEM);

    init_kernel<<<256, 256>>>();

    // 0) bf16 hi/lo splits
    split_bf16<<<1024, 256>>>(x, xh, xl, 16384L * 512);
    split_bf16<<<256, 256>>>(w_qkv, wh, wl, 1536L * 512);
    split_bf16<<<128, 256>>>(agent, agh, agl, 8L * 256 * 64);

    // 1) qkv = x @ w_qkv^T via bf16x3 mma.sync (verified 8-warp config)
    k1_mma_kernel<<<dim3(12, 128), 256, K1_SMEM>>>(xh, xl, wh, wl, qkv);

    // 2) fused: ka softmax-partials + kv accumulation (16 splits)
    attn_kv_kernel<<<dim3(16, 16), 256, A_SMEM>>>(qkv, agh, agl, kv, ksum);

    // 3) normalize kv
    kv_div_kernel<<<1024, 256>>>(kv, ksum);

    // 4) threshold scalar
    thresh_kernel<<<512, 256>>>(kv, w_thresh);

    // 5) mask/denoise + second softmax -> kv2 transposed bf16 hi/lo
    kv2_kernel<<<4096, 64>>>(kv, kth, ktl, w_noise, b_noise, w_mask, b_mask, b_thresh);

    // 6) fused: qa softmax + out = qa @ kv2
    attn_out_kernel<<<dim3(128, 16), 256, B_SMEM>>>(qkv, agh, agl, kth, ktl, out);
}